// round 2
// baseline (speedup 1.0000x reference)
#include <cuda_runtime.h>
#include <cuda_bf16.h>
#include <math.h>

// ---------------- problem constants (fixed by dataset) ----------------
#define NN    100000
#define EE    1600000
#define DIN   256
#define DOUT  64
#define KPROP 10
#define ALPHA 0.1f

// ---------------- static device scratch (no allocs allowed) ----------
__device__ float g_h  [(size_t)NN * DOUT];
__device__ float g_z0 [(size_t)NN * DOUT];
__device__ float g_z1 [(size_t)NN * DOUT];
__device__ float g_dinv[NN];
__device__ float g_ew  [EE];
__device__ float g_Wt  [DIN * DOUT];

// buffer selector: 0 -> g_z0, 1 -> g_z1, 2 -> g_h, 3 -> external (d_out)
__device__ __forceinline__ const float* zsel_c(int s, const float* ext) {
    return s == 0 ? g_z0 : s == 1 ? g_z1 : s == 2 ? g_h : ext;
}
__device__ __forceinline__ float* zsel(int s, float* ext) {
    return s == 0 ? g_z0 : s == 1 ? g_z1 : ext;
}

// ---------------- helpers --------------------------------------------
__device__ __forceinline__ void red_add_v4(float4* p, float a, float b, float c, float d) {
    asm volatile("red.global.add.v4.f32 [%0], {%1, %2, %3, %4};"
                 :: "l"(p), "f"(a), "f"(b), "f"(c), "f"(d) : "memory");
}

// ---------------- W transpose: Wt[k*64+c] = W[c*256+k] ----------------
__global__ void transpose_w(const float* __restrict__ W) {
    int i = blockIdx.x * blockDim.x + threadIdx.x;
    if (i >= DIN * DOUT) return;
    int k = i >> 6;           // 0..255
    int c = i & 63;           // 0..63
    g_Wt[i] = W[c * DIN + k];
}

// ---------------- GEMM + bias + ReLU: h = relu(x @ W^T + b) -----------
// block: 256 threads, 96 rows x 64 cols per block, K chunked by 64.
#define GR 96
#define KC 64
#define XS 68   // padded row stride

__global__ __launch_bounds__(256) void gemm_relu(
    const float* __restrict__ x, const float* __restrict__ b)
{
    __shared__ float xs[GR * XS];     // 96x64 x-tile (padded)
    __shared__ float ws[KC * DOUT];   // 64x64 w-tile (k-major)

    const int tid  = threadIdx.x;
    const int row0 = blockIdx.x * GR;
    const int c0   = (tid & 15) << 2;   // 4 cols per thread
    const int rs   = tid >> 4;          // 0..15; rows rs + 16*j, j<6

    float acc[6][4];
#pragma unroll
    for (int j = 0; j < 6; j++)
#pragma unroll
        for (int q = 0; q < 4; q++) acc[j][q] = 0.f;

    for (int ck = 0; ck < DIN / KC; ck++) {
        __syncthreads();
        // load W tile (linear copy, k-major already)
        {
            const float4* wsrc = (const float4*)(g_Wt + ck * (KC * DOUT));
            float4*       wdst = (float4*)ws;
#pragma unroll
            for (int it = 0; it < 4; it++)
                wdst[tid + 256 * it] = wsrc[tid + 256 * it];
        }
        // load x tile (96 rows x 64 k)
#pragma unroll
        for (int it = 0; it < 6; it++) {
            int i  = tid + 256 * it;
            int r  = i >> 4;
            int k4 = (i & 15) << 2;
            int gr = row0 + r;
            float4 v = make_float4(0.f, 0.f, 0.f, 0.f);
            if (gr < NN)
                v = *(const float4*)(x + (size_t)gr * DIN + ck * KC + k4);
            *(float4*)&xs[r * XS + k4] = v;
        }
        __syncthreads();

#pragma unroll 8
        for (int kk = 0; kk < KC; kk++) {
            float4 w4 = *(const float4*)&ws[kk * DOUT + c0];
#pragma unroll
            for (int j = 0; j < 6; j++) {
                float xv = xs[(rs + 16 * j) * XS + kk];
                acc[j][0] += xv * w4.x;
                acc[j][1] += xv * w4.y;
                acc[j][2] += xv * w4.z;
                acc[j][3] += xv * w4.w;
            }
        }
    }

    float4 bb = *(const float4*)(b + c0);
#pragma unroll
    for (int j = 0; j < 6; j++) {
        int row = row0 + rs + 16 * j;
        if (row < NN) {
            float4 o;
            o.x = fmaxf(acc[j][0] + bb.x, 0.f);
            o.y = fmaxf(acc[j][1] + bb.y, 0.f);
            o.z = fmaxf(acc[j][2] + bb.z, 0.f);
            o.w = fmaxf(acc[j][3] + bb.w, 0.f);
            *(float4*)(g_h + (size_t)row * DOUT + c0) = o;
        }
    }
}

// ---------------- degree / normalization ------------------------------
__global__ void deg_init() {
    int i = blockIdx.x * blockDim.x + threadIdx.x;
    if (i < NN) g_dinv[i] = 1.0f;   // self-loop
}

__global__ void deg_acc(const int* __restrict__ dst) {
    int e = blockIdx.x * blockDim.x + threadIdx.x;
    if (e < EE) atomicAdd(&g_dinv[dst[e]], 1.0f);
}

__global__ void make_dinv() {
    int i = blockIdx.x * blockDim.x + threadIdx.x;
    if (i < NN) g_dinv[i] = rsqrtf(g_dinv[i]);   // deg >= 1 always (self-loop)
}

// edge weight folds the (1-alpha)=0.9 propagation factor
__global__ void edge_weights(const int* __restrict__ src, const int* __restrict__ dst) {
    int e = blockIdx.x * blockDim.x + threadIdx.x;
    if (e < EE) g_ew[e] = 0.9f * g_dinv[src[e]] * g_dinv[dst[e]];
}

// ---------------- per-step: out = alpha*h + 0.9*dinv^2 * z ------------
__global__ void init_step(int out_sel, int in_sel, float* __restrict__ ext) {
    int t = blockIdx.x * blockDim.x + threadIdx.x;
    if (t >= NN * (DOUT / 4)) return;
    const float* zin = zsel_c(in_sel, ext);
    float*       out = zsel(out_sel, ext);
    int node = t >> 4;                 // 16 float4 per node
    float di = g_dinv[node];
    float sw = 0.9f * di * di;
    float4 z  = ((const float4*)zin)[t];
    float4 hh = ((const float4*)g_h)[t];
    float4 o;
    o.x = ALPHA * hh.x + sw * z.x;
    o.y = ALPHA * hh.y + sw * z.y;
    o.z = ALPHA * hh.z + sw * z.z;
    o.w = ALPHA * hh.w + sw * z.w;
    ((float4*)out)[t] = o;
}

// ---------------- per-step: scatter edges (8 threads / edge) ----------
__global__ __launch_bounds__(256) void edge_scatter(
    const int* __restrict__ src, const int* __restrict__ dst,
    int in_sel, int out_sel, float* __restrict__ ext)
{
    unsigned t = blockIdx.x * blockDim.x + threadIdx.x;
    unsigned e = t >> 3;
    if (e >= EE) return;
    unsigned lane = t & 7;

    const float* zin  = zsel_c(in_sel, ext);
    float*       zout = zsel(out_sel, ext);

    int   s = src[e];
    int   d = dst[e];
    float w = g_ew[e];

    const float4* zi = (const float4*)(zin + (size_t)s * DOUT);
    float4 a = zi[lane];
    float4 b = zi[lane + 8];

    float4* zo = (float4*)(zout + (size_t)d * DOUT);
    red_add_v4(zo + lane,     a.x * w, a.y * w, a.z * w, a.w * w);
    red_add_v4(zo + lane + 8, b.x * w, b.y * w, b.z * w, b.w * w);
}

// ---------------- launch ----------------------------------------------
extern "C" void kernel_launch(void* const* d_in, const int* in_sizes, int n_in,
                              void* d_out, int out_size) {
    const float* x  = (const float*)d_in[0];
    const int*   ei = (const int*)  d_in[1];
    // d_in[2] = W, d_in[3] = b
    const float* W  = (const float*)d_in[2];
    const float* b  = (const float*)d_in[3];
    float* out = (float*)d_out;

    const int* se = ei;        // src row
    const int* de = ei + EE;   // dst row

    // dense stack
    transpose_w<<<(DIN * DOUT + 255) / 256, 256>>>(W);
    gemm_relu<<<(NN + GR - 1) / GR, 256>>>(x, b);

    // gcn_norm (once)
    deg_init<<<(NN + 255) / 256, 256>>>();
    deg_acc<<<(EE + 255) / 256, 256>>>(de);
    make_dinv<<<(NN + 255) / 256, 256>>>();
    edge_weights<<<(EE + 255) / 256, 256>>>(se, de);

    // K-step APPNP propagation (ping-pong; last step lands in d_out)
    int cur = 2;  // g_h
    const int init_grid = (NN * (DOUT / 4) + 255) / 256;
    const int scat_grid = ((unsigned)EE * 8 + 255) / 256;
    for (int k = 0; k < KPROP; k++) {
        int nxt = (k == KPROP - 1) ? 3 : (k & 1);
        init_step<<<init_grid, 256>>>(nxt, cur, out);
        edge_scatter<<<scat_grid, 256>>>(se, de, cur, nxt, out);
        cur = nxt;
    }
}

// round 3
// speedup vs baseline: 1.7098x; 1.7098x over previous
#include <cuda_runtime.h>
#include <cuda_bf16.h>
#include <math.h>

// ---------------- problem constants ----------------
#define NN    100000
#define EE    1600000
#define DIN   256
#define DOUT  64
#define KPROP 10
#define ALPHA 0.1f

// ---------------- static device scratch ----------------
__device__ float g_h  [(size_t)NN * DOUT];
__device__ float g_z0 [(size_t)NN * DOUT];
__device__ float g_z1 [(size_t)NN * DOUT];
__device__ float g_dinv[NN];
__device__ float g_Wt  [DIN * DOUT];

__device__ int   g_cnt   [NN];
__device__ int   g_cursor[NN];
__device__ int   g_rowstart[NN + 1];
__device__ int   g_csrc[EE];
__device__ float g_cw  [EE];
__device__ int   g_blksum[128];
__device__ int   g_blkoff[128];

#define SCAN_BS  1024                       // elements per scan block
#define SCAN_NB  ((NN + SCAN_BS - 1) / SCAN_BS)   // 98
__device__ int g_rowtmp[NN];

// buffer selector: 0 -> g_z0, 1 -> g_z1, 2 -> g_h, 3 -> external (d_out)
__device__ __forceinline__ const float* zsel_c(int s, const float* ext) {
    return s == 0 ? g_z0 : s == 1 ? g_z1 : s == 2 ? g_h : ext;
}
__device__ __forceinline__ float* zsel(int s, float* ext) {
    return s == 0 ? g_z0 : s == 1 ? g_z1 : ext;
}

// ---------------- W transpose ----------------
__global__ void transpose_w(const float* __restrict__ W) {
    int i = blockIdx.x * blockDim.x + threadIdx.x;
    if (i >= DIN * DOUT) return;
    int k = i >> 6;
    int c = i & 63;
    g_Wt[i] = W[c * DIN + k];
}

// ---------------- GEMM + bias + ReLU ----------------
#define GR 96
#define KC 64
#define XS 68

__global__ __launch_bounds__(256) void gemm_relu(
    const float* __restrict__ x, const float* __restrict__ b)
{
    __shared__ float xs[GR * XS];
    __shared__ float ws[KC * DOUT];

    const int tid  = threadIdx.x;
    const int row0 = blockIdx.x * GR;
    const int c0   = (tid & 15) << 2;
    const int rs   = tid >> 4;

    float acc[6][4];
#pragma unroll
    for (int j = 0; j < 6; j++)
#pragma unroll
        for (int q = 0; q < 4; q++) acc[j][q] = 0.f;

    for (int ck = 0; ck < DIN / KC; ck++) {
        __syncthreads();
        {
            const float4* wsrc = (const float4*)(g_Wt + ck * (KC * DOUT));
            float4*       wdst = (float4*)ws;
#pragma unroll
            for (int it = 0; it < 4; it++)
                wdst[tid + 256 * it] = wsrc[tid + 256 * it];
        }
#pragma unroll
        for (int it = 0; it < 6; it++) {
            int i  = tid + 256 * it;
            int r  = i >> 4;
            int k4 = (i & 15) << 2;
            int gr = row0 + r;
            float4 v = make_float4(0.f, 0.f, 0.f, 0.f);
            if (gr < NN)
                v = *(const float4*)(x + (size_t)gr * DIN + ck * KC + k4);
            *(float4*)&xs[r * XS + k4] = v;
        }
        __syncthreads();

#pragma unroll 8
        for (int kk = 0; kk < KC; kk++) {
            float4 w4 = *(const float4*)&ws[kk * DOUT + c0];
#pragma unroll
            for (int j = 0; j < 6; j++) {
                float xv = xs[(rs + 16 * j) * XS + kk];
                acc[j][0] += xv * w4.x;
                acc[j][1] += xv * w4.y;
                acc[j][2] += xv * w4.z;
                acc[j][3] += xv * w4.w;
            }
        }
    }

    float4 bb = *(const float4*)(b + c0);
#pragma unroll
    for (int j = 0; j < 6; j++) {
        int row = row0 + rs + 16 * j;
        if (row < NN) {
            float4 o;
            o.x = fmaxf(acc[j][0] + bb.x, 0.f);
            o.y = fmaxf(acc[j][1] + bb.y, 0.f);
            o.z = fmaxf(acc[j][2] + bb.z, 0.f);
            o.w = fmaxf(acc[j][3] + bb.w, 0.f);
            *(float4*)(g_h + (size_t)row * DOUT + c0) = o;
        }
    }
}

// ---------------- degree count + dinv ----------------
__global__ void cnt_init() {
    int i = blockIdx.x * blockDim.x + threadIdx.x;
    if (i < NN) { g_cnt[i] = 0; g_cursor[i] = 0; }
}

__global__ void deg_acc(const int* __restrict__ dst) {
    int e = blockIdx.x * blockDim.x + threadIdx.x;
    if (e < EE) atomicAdd(&g_cnt[dst[e]], 1);
}

__global__ void make_dinv() {
    int i = blockIdx.x * blockDim.x + threadIdx.x;
    if (i < NN) g_dinv[i] = rsqrtf((float)(g_cnt[i] + 1));   // +1 self-loop
}

// ---------------- exclusive scan of g_cnt -> g_rowstart ----------------
__global__ __launch_bounds__(256) void scanA() {
    __shared__ int sh[256];
    int tid  = threadIdx.x;
    int base = blockIdx.x * SCAN_BS + tid * 4;
    int v[4];
#pragma unroll
    for (int q = 0; q < 4; q++) {
        int idx = base + q;
        v[q] = (idx < NN) ? g_cnt[idx] : 0;
    }
    int tsum = v[0] + v[1] + v[2] + v[3];
    sh[tid] = tsum;
    __syncthreads();
    // Hillis-Steele inclusive scan
    for (int off = 1; off < 256; off <<= 1) {
        int x = (tid >= off) ? sh[tid - off] : 0;
        __syncthreads();
        sh[tid] += x;
        __syncthreads();
    }
    int run = sh[tid] - tsum;   // exclusive prefix of this thread
#pragma unroll
    for (int q = 0; q < 4; q++) {
        int idx = base + q;
        if (idx < NN) g_rowtmp[idx] = run;
        run += v[q];
    }
    if (tid == 255) g_blksum[blockIdx.x] = sh[255];
}

__global__ __launch_bounds__(128) void scanB() {
    __shared__ int sh[128];
    int tid = threadIdx.x;
    int v = (tid < SCAN_NB) ? g_blksum[tid] : 0;
    sh[tid] = v;
    __syncthreads();
    for (int off = 1; off < 128; off <<= 1) {
        int x = (tid >= off) ? sh[tid - off] : 0;
        __syncthreads();
        sh[tid] += x;
        __syncthreads();
    }
    g_blkoff[tid] = sh[tid] - v;
}

__global__ void scanC() {
    int i = blockIdx.x * blockDim.x + threadIdx.x;
    if (i < NN) g_rowstart[i] = g_rowtmp[i] + g_blkoff[i / SCAN_BS];
    if (i == 0) g_rowstart[NN] = EE;
}

// ---------------- CSR fill (counting-sort permute) ----------------
__global__ void csr_fill(const int* __restrict__ src, const int* __restrict__ dst) {
    int e = blockIdx.x * blockDim.x + threadIdx.x;
    if (e >= EE) return;
    int d = dst[e];
    int s = src[e];
    int pos = g_rowstart[d] + atomicAdd(&g_cursor[d], 1);
    g_csrc[pos] = s;
    g_cw[pos]   = 0.9f * g_dinv[s] * g_dinv[d];
}

// ---------------- fused APPNP step (pull / CSR gather) ----------------
// one warp per node; lane owns float2 columns [2*lane, 2*lane+1]
#define WPB 8
__global__ __launch_bounds__(WPB * 32) void appnp_step(int in_sel, int out_sel,
                                                       float* __restrict__ ext) {
    int warp = threadIdx.x >> 5;
    int lane = threadIdx.x & 31;
    int node = blockIdx.x * WPB + warp;
    if (node >= NN) return;

    const float2* zin  = (const float2*)zsel_c(in_sel, ext);
    float2*       zout = (float2*)zsel(out_sel, ext);

    float di = g_dinv[node];
    float sw = 0.9f * di * di;
    int   ri = node * 32 + lane;

    float2 hd = ((const float2*)g_h)[ri];
    float2 zd = zin[ri];
    float accx = ALPHA * hd.x + sw * zd.x;
    float accy = ALPHA * hd.y + sw * zd.y;

    int j  = g_rowstart[node];
    int j1 = g_rowstart[node + 1];

    // unroll 4 for MLP
    for (; j + 4 <= j1; j += 4) {
        int   s0 = g_csrc[j],     s1 = g_csrc[j + 1];
        int   s2 = g_csrc[j + 2], s3 = g_csrc[j + 3];
        float w0 = g_cw[j],       w1 = g_cw[j + 1];
        float w2 = g_cw[j + 2],   w3 = g_cw[j + 3];
        float2 a0 = zin[s0 * 32 + lane];
        float2 a1 = zin[s1 * 32 + lane];
        float2 a2 = zin[s2 * 32 + lane];
        float2 a3 = zin[s3 * 32 + lane];
        accx += w0 * a0.x + w1 * a1.x + w2 * a2.x + w3 * a3.x;
        accy += w0 * a0.y + w1 * a1.y + w2 * a2.y + w3 * a3.y;
    }
    for (; j < j1; j++) {
        int   s = g_csrc[j];
        float w = g_cw[j];
        float2 a = zin[s * 32 + lane];
        accx += w * a.x;
        accy += w * a.y;
    }

    float2 o; o.x = accx; o.y = accy;
    zout[ri] = o;
}

// ---------------- launch ----------------
extern "C" void kernel_launch(void* const* d_in, const int* in_sizes, int n_in,
                              void* d_out, int out_size) {
    const float* x  = (const float*)d_in[0];
    const int*   ei = (const int*)  d_in[1];
    const float* W  = (const float*)d_in[2];
    const float* b  = (const float*)d_in[3];
    float* out = (float*)d_out;

    const int* se = ei;        // src row
    const int* de = ei + EE;   // dst row

    // dense stack
    transpose_w<<<(DIN * DOUT + 255) / 256, 256>>>(W);
    gemm_relu<<<(NN + GR - 1) / GR, 256>>>(x, b);

    // degree + normalization + CSR build
    cnt_init<<<(NN + 255) / 256, 256>>>();
    deg_acc<<<(EE + 255) / 256, 256>>>(de);
    make_dinv<<<(NN + 255) / 256, 256>>>();
    scanA<<<SCAN_NB, 256>>>();
    scanB<<<1, 128>>>();
    scanC<<<(NN + 255) / 256, 256>>>();
    csr_fill<<<(EE + 255) / 256, 256>>>(se, de);

    // K-step APPNP propagation (fused init + gather; last step -> d_out)
    int cur = 2;  // g_h
    const int step_grid = (NN + WPB - 1) / WPB;
    for (int k = 0; k < KPROP; k++) {
        int nxt = (k == KPROP - 1) ? 3 : (k & 1);
        appnp_step<<<step_grid, WPB * 32>>>(cur, nxt, out);
        cur = nxt;
    }
}

// round 4
// speedup vs baseline: 1.8295x; 1.0700x over previous
#include <cuda_runtime.h>
#include <cuda_fp16.h>
#include <math.h>

// ---------------- problem constants ----------------
#define NN    100000
#define EE    1600000
#define DIN   256
#define DOUT  64
#define KPROP 10
#define ALPHA 0.1f

// ---------------- static device scratch ----------------
__device__ float  g_h  [(size_t)NN * DOUT];
__device__ __half g_zhA[(size_t)NN * DOUT];
__device__ __half g_zhB[(size_t)NN * DOUT];
__device__ float  g_dinv[NN];
__device__ float  g_Wt  [DIN * DOUT];

__device__ int   g_cnt   [NN];
__device__ int   g_cursor[NN];
__device__ int   g_rowstart[NN + 1];
__device__ int   g_csrc[EE];
__device__ float g_cw  [EE];
__device__ int   g_blksum[128];
__device__ int   g_blkoff[128];

#define SCAN_BS  1024
#define SCAN_NB  ((NN + SCAN_BS - 1) / SCAN_BS)   // 98
__device__ int g_rowtmp[NN];

// ---------------- W transpose ----------------
__global__ void transpose_w(const float* __restrict__ W) {
    int i = blockIdx.x * blockDim.x + threadIdx.x;
    if (i >= DIN * DOUT) return;
    int k = i >> 6;
    int c = i & 63;
    g_Wt[i] = W[c * DIN + k];
}

// ---------------- GEMM + bias + ReLU ----------------
#define GR 96
#define KC 64
#define XS 68

__global__ __launch_bounds__(256) void gemm_relu(
    const float* __restrict__ x, const float* __restrict__ b)
{
    __shared__ float xs[GR * XS];
    __shared__ float ws[KC * DOUT];

    const int tid  = threadIdx.x;
    const int row0 = blockIdx.x * GR;
    const int c0   = (tid & 15) << 2;
    const int rs   = tid >> 4;

    float acc[6][4];
#pragma unroll
    for (int j = 0; j < 6; j++)
#pragma unroll
        for (int q = 0; q < 4; q++) acc[j][q] = 0.f;

    for (int ck = 0; ck < DIN / KC; ck++) {
        __syncthreads();
        {
            const float4* wsrc = (const float4*)(g_Wt + ck * (KC * DOUT));
            float4*       wdst = (float4*)ws;
#pragma unroll
            for (int it = 0; it < 4; it++)
                wdst[tid + 256 * it] = wsrc[tid + 256 * it];
        }
#pragma unroll
        for (int it = 0; it < 6; it++) {
            int i  = tid + 256 * it;
            int r  = i >> 4;
            int k4 = (i & 15) << 2;
            int gr = row0 + r;
            float4 v = make_float4(0.f, 0.f, 0.f, 0.f);
            if (gr < NN)
                v = *(const float4*)(x + (size_t)gr * DIN + ck * KC + k4);
            *(float4*)&xs[r * XS + k4] = v;
        }
        __syncthreads();

#pragma unroll 8
        for (int kk = 0; kk < KC; kk++) {
            float4 w4 = *(const float4*)&ws[kk * DOUT + c0];
#pragma unroll
            for (int j = 0; j < 6; j++) {
                float xv = xs[(rs + 16 * j) * XS + kk];
                acc[j][0] += xv * w4.x;
                acc[j][1] += xv * w4.y;
                acc[j][2] += xv * w4.z;
                acc[j][3] += xv * w4.w;
            }
        }
    }

    float4 bb = *(const float4*)(b + c0);
#pragma unroll
    for (int j = 0; j < 6; j++) {
        int row = row0 + rs + 16 * j;
        if (row < NN) {
            float4 o;
            o.x = fmaxf(acc[j][0] + bb.x, 0.f);
            o.y = fmaxf(acc[j][1] + bb.y, 0.f);
            o.z = fmaxf(acc[j][2] + bb.z, 0.f);
            o.w = fmaxf(acc[j][3] + bb.w, 0.f);
            *(float4*)(g_h + (size_t)row * DOUT + c0) = o;
        }
    }
}

// ---------------- h -> half (initial z state) ----------------
__global__ void h_to_half() {
    int t = blockIdx.x * blockDim.x + threadIdx.x;
    if (t >= NN * (DOUT / 2)) return;
    float2 v = ((const float2*)g_h)[t];
    ((__half2*)g_zhA)[t] = __floats2half2_rn(v.x, v.y);
}

// ---------------- degree count + dinv ----------------
__global__ void cnt_init() {
    int i = blockIdx.x * blockDim.x + threadIdx.x;
    if (i < NN) { g_cnt[i] = 0; g_cursor[i] = 0; }
}

__global__ void deg_acc(const int* __restrict__ dst) {
    int e = blockIdx.x * blockDim.x + threadIdx.x;
    if (e < EE) atomicAdd(&g_cnt[dst[e]], 1);
}

__global__ void make_dinv() {
    int i = blockIdx.x * blockDim.x + threadIdx.x;
    if (i < NN) g_dinv[i] = rsqrtf((float)(g_cnt[i] + 1));
}

// ---------------- exclusive scan of g_cnt -> g_rowstart ----------------
__global__ __launch_bounds__(256) void scanA() {
    __shared__ int sh[256];
    int tid  = threadIdx.x;
    int base = blockIdx.x * SCAN_BS + tid * 4;
    int v[4];
#pragma unroll
    for (int q = 0; q < 4; q++) {
        int idx = base + q;
        v[q] = (idx < NN) ? g_cnt[idx] : 0;
    }
    int tsum = v[0] + v[1] + v[2] + v[3];
    sh[tid] = tsum;
    __syncthreads();
    for (int off = 1; off < 256; off <<= 1) {
        int x = (tid >= off) ? sh[tid - off] : 0;
        __syncthreads();
        sh[tid] += x;
        __syncthreads();
    }
    int run = sh[tid] - tsum;
#pragma unroll
    for (int q = 0; q < 4; q++) {
        int idx = base + q;
        if (idx < NN) g_rowtmp[idx] = run;
        run += v[q];
    }
    if (tid == 255) g_blksum[blockIdx.x] = sh[255];
}

__global__ __launch_bounds__(128) void scanB() {
    __shared__ int sh[128];
    int tid = threadIdx.x;
    int v = (tid < SCAN_NB) ? g_blksum[tid] : 0;
    sh[tid] = v;
    __syncthreads();
    for (int off = 1; off < 128; off <<= 1) {
        int x = (tid >= off) ? sh[tid - off] : 0;
        __syncthreads();
        sh[tid] += x;
        __syncthreads();
    }
    g_blkoff[tid] = sh[tid] - v;
}

__global__ void scanC() {
    int i = blockIdx.x * blockDim.x + threadIdx.x;
    if (i < NN) g_rowstart[i] = g_rowtmp[i] + g_blkoff[i / SCAN_BS];
    if (i == 0) g_rowstart[NN] = EE;
}

// ---------------- CSR fill (counting-sort permute) ----------------
__global__ void csr_fill(const int* __restrict__ src, const int* __restrict__ dst) {
    int e = blockIdx.x * blockDim.x + threadIdx.x;
    if (e >= EE) return;
    int d = dst[e];
    int s = src[e];
    int pos = g_rowstart[d] + atomicAdd(&g_cursor[d], 1);
    g_csrc[pos] = s;
    g_cw[pos]   = 0.9f * g_dinv[s] * g_dinv[d];
}

// ---------------- fused APPNP step (pull, half z state) ----------------
// one warp per node; lane owns half2 columns [2*lane, 2*lane+1]
#define WPB 8
__global__ __launch_bounds__(WPB * 32) void appnp_step(int in_sel, int out_sel,
                                                       float* __restrict__ ext) {
    int warp = threadIdx.x >> 5;
    int lane = threadIdx.x & 31;
    int node = blockIdx.x * WPB + warp;
    if (node >= NN) return;

    const __half2* zin = (in_sel == 0) ? (const __half2*)g_zhA
                                       : (const __half2*)g_zhB;

    float di = g_dinv[node];
    float sw = 0.9f * di * di;
    int   ri = node * 32 + lane;

    float2 hd = ((const float2*)g_h)[ri];
    float2 zd = __half22float2(zin[ri]);
    float accx = ALPHA * hd.x + sw * zd.x;
    float accy = ALPHA * hd.y + sw * zd.y;

    int j  = g_rowstart[node];
    int j1 = g_rowstart[node + 1];

    for (; j + 4 <= j1; j += 4) {
        int   s0 = g_csrc[j],     s1 = g_csrc[j + 1];
        int   s2 = g_csrc[j + 2], s3 = g_csrc[j + 3];
        float w0 = g_cw[j],       w1 = g_cw[j + 1];
        float w2 = g_cw[j + 2],   w3 = g_cw[j + 3];
        float2 a0 = __half22float2(zin[s0 * 32 + lane]);
        float2 a1 = __half22float2(zin[s1 * 32 + lane]);
        float2 a2 = __half22float2(zin[s2 * 32 + lane]);
        float2 a3 = __half22float2(zin[s3 * 32 + lane]);
        accx += w0 * a0.x + w1 * a1.x + w2 * a2.x + w3 * a3.x;
        accy += w0 * a0.y + w1 * a1.y + w2 * a2.y + w3 * a3.y;
    }
    for (; j < j1; j++) {
        int   s = g_csrc[j];
        float w = g_cw[j];
        float2 a = __half22float2(zin[s * 32 + lane]);
        accx += w * a.x;
        accy += w * a.y;
    }

    if (out_sel == 3) {
        float2 o; o.x = accx; o.y = accy;
        ((float2*)ext)[ri] = o;
    } else {
        __half2* zout = (out_sel == 0) ? (__half2*)g_zhA : (__half2*)g_zhB;
        zout[ri] = __floats2half2_rn(accx, accy);
    }
}

// ---------------- launch ----------------
extern "C" void kernel_launch(void* const* d_in, const int* in_sizes, int n_in,
                              void* d_out, int out_size) {
    const float* x  = (const float*)d_in[0];
    const int*   ei = (const int*)  d_in[1];
    const float* W  = (const float*)d_in[2];
    const float* b  = (const float*)d_in[3];
    float* out = (float*)d_out;

    const int* se = ei;        // src row
    const int* de = ei + EE;   // dst row

    // dense stack
    transpose_w<<<(DIN * DOUT + 255) / 256, 256>>>(W);
    gemm_relu<<<(NN + GR - 1) / GR, 256>>>(x, b);
    h_to_half<<<(NN * (DOUT / 2) + 255) / 256, 256>>>();

    // degree + normalization + CSR build
    cnt_init<<<(NN + 255) / 256, 256>>>();
    deg_acc<<<(EE + 255) / 256, 256>>>(de);
    make_dinv<<<(NN + 255) / 256, 256>>>();
    scanA<<<SCAN_NB, 256>>>();
    scanB<<<1, 128>>>();
    scanC<<<(NN + 255) / 256, 256>>>();
    csr_fill<<<(EE + 255) / 256, 256>>>(se, de);

    // K-step APPNP propagation; state ping-pongs A<->B; last step -> d_out fp32
    const int step_grid = (NN + WPB - 1) / WPB;
    for (int k = 0; k < KPROP; k++) {
        int in_sel  = k & 1;                       // 0=A, 1=B
        int out_sel = (k == KPROP - 1) ? 3 : 1 - (k & 1);
        appnp_step<<<step_grid, WPB * 32>>>(in_sel, out_sel, out);
    }
}

// round 6
// speedup vs baseline: 2.0886x; 1.1417x over previous
#include <cuda_runtime.h>
#include <cuda_fp16.h>
#include <cstdint>
#include <math.h>

// ---------------- problem constants ----------------
#define NN    100000
#define EE    1600000
#define DIN   256
#define DOUT  64
#define KPROP 10
#define ALPHA 0.1f

// ---------------- static device scratch ----------------
__device__ __half g_hh [(size_t)NN * DOUT];   // h in fp16
__device__ __half g_zhA[(size_t)NN * DOUT];
__device__ __half g_zhB[(size_t)NN * DOUT];
__device__ float  g_dinv[NN];

__device__ int   g_cnt   [NN];
__device__ int   g_cursor[NN];
__device__ int   g_rowstart[NN + 1];
__device__ int   g_csrc[EE];
__device__ float g_cw  [EE];
__device__ int   g_blksum[128];
__device__ int   g_blkoff[128];

#define SCAN_BS  1024
#define SCAN_NB  ((NN + SCAN_BS - 1) / SCAN_BS)   // 98
__device__ int g_rowtmp[NN];

// ---------------- tensor-core GEMM + bias + ReLU ----------------
// h = relu(x @ W^T + b); writes g_hh (fp16) and g_zhA (initial z state).
// block: 256 threads (8 warps), 128 rows x 64 cols; K chunked by 64.
#define GROWS 128
#define XPAD  72   // half stride

__device__ __forceinline__ void mma_16816(float* c, const uint32_t* a,
                                          uint32_t b0, uint32_t b1) {
    asm volatile(
        "mma.sync.aligned.m16n8k16.row.col.f32.f16.f16.f32 "
        "{%0,%1,%2,%3}, {%4,%5,%6,%7}, {%8,%9}, {%0,%1,%2,%3};"
        : "+f"(c[0]), "+f"(c[1]), "+f"(c[2]), "+f"(c[3])
        : "r"(a[0]), "r"(a[1]), "r"(a[2]), "r"(a[3]), "r"(b0), "r"(b1));
}

__global__ __launch_bounds__(256) void gemm_relu(
    const float* __restrict__ x, const float* __restrict__ W,
    const float* __restrict__ b)
{
    __shared__ __half xs[GROWS * XPAD];   // 18.4 KB
    __shared__ __half ws[DOUT * XPAD];    //  9.2 KB

    const int tid  = threadIdx.x;
    const int warp = tid >> 5;
    const int lane = tid & 31;
    const int gid  = lane >> 2;     // 0..7
    const int tg   = lane & 3;      // 0..3
    const int row0 = blockIdx.x * GROWS;
    const int wrow = warp * 16;

    float acc[8][4];
#pragma unroll
    for (int nt = 0; nt < 8; nt++)
#pragma unroll
        for (int q = 0; q < 4; q++) acc[nt][q] = 0.f;

    for (int kc = 0; kc < DIN / 64; kc++) {
        const int k0 = kc * 64;
        __syncthreads();
        // ---- load W chunk [64 rows (n)][64 k] fp32 -> half smem ----
        {
            int n  = tid >> 2;             // 0..63
            int kq = (tid & 3) * 16;       // 0,16,32,48
            const float4* wsrc = (const float4*)(W + (size_t)n * DIN + k0 + kq);
#pragma unroll
            for (int i = 0; i < 4; i++) {
                float4 v = wsrc[i];
                __half2* d = (__half2*)&ws[n * XPAD + kq + i * 4];
                d[0] = __floats2half2_rn(v.x, v.y);
                d[1] = __floats2half2_rn(v.z, v.w);
            }
        }
        // ---- load x chunk [128 rows][64 k] fp32 -> half smem ----
        {
            int r  = tid >> 1;             // 0..127
            int kq = (tid & 1) * 32;       // 0 or 32
            int gr = row0 + r;
            if (gr < NN) {
                const float4* xsrc = (const float4*)(x + (size_t)gr * DIN + k0 + kq);
#pragma unroll
                for (int i = 0; i < 8; i++) {
                    float4 v = xsrc[i];
                    __half2* d = (__half2*)&xs[r * XPAD + kq + i * 4];
                    d[0] = __floats2half2_rn(v.x, v.y);
                    d[1] = __floats2half2_rn(v.z, v.w);
                }
            } else {
                __half2 z2 = __floats2half2_rn(0.f, 0.f);
                __half2* d = (__half2*)&xs[r * XPAD + kq];
#pragma unroll
                for (int i = 0; i < 16; i++) d[i] = z2;
            }
        }
        __syncthreads();

        // ---- 4 k-steps of mma ----
#pragma unroll
        for (int ks = 0; ks < 4; ks++) {
            int kb = ks * 16 + 2 * tg;
            uint32_t a[4];
            a[0] = *(const uint32_t*)&xs[(wrow + gid)     * XPAD + kb];
            a[1] = *(const uint32_t*)&xs[(wrow + gid + 8) * XPAD + kb];
            a[2] = *(const uint32_t*)&xs[(wrow + gid)     * XPAD + kb + 8];
            a[3] = *(const uint32_t*)&xs[(wrow + gid + 8) * XPAD + kb + 8];
#pragma unroll
            for (int nt = 0; nt < 8; nt++) {
                uint32_t b0 = *(const uint32_t*)&ws[(nt * 8 + gid) * XPAD + kb];
                uint32_t b1 = *(const uint32_t*)&ws[(nt * 8 + gid) * XPAD + kb + 8];
                mma_16816(acc[nt], a, b0, b1);
            }
        }
    }

    // ---- epilogue: bias + relu -> g_hh and g_zhA (fp16) ----
    int r0 = row0 + wrow + gid;
    int r1 = r0 + 8;
#pragma unroll
    for (int nt = 0; nt < 8; nt++) {
        int cn = nt * 8 + 2 * tg;
        float b0v = b[cn], b1v = b[cn + 1];
        int ci = (cn >> 1);   // half2 column index (0..31)
        if (r0 < NN) {
            __half2 v = __floats2half2_rn(fmaxf(acc[nt][0] + b0v, 0.f),
                                          fmaxf(acc[nt][1] + b1v, 0.f));
            ((__half2*)g_hh )[r0 * 32 + ci] = v;
            ((__half2*)g_zhA)[r0 * 32 + ci] = v;
        }
        if (r1 < NN) {
            __half2 v = __floats2half2_rn(fmaxf(acc[nt][2] + b0v, 0.f),
                                          fmaxf(acc[nt][3] + b1v, 0.f));
            ((__half2*)g_hh )[r1 * 32 + ci] = v;
            ((__half2*)g_zhA)[r1 * 32 + ci] = v;
        }
    }
}

// ---------------- degree count + scan + CSR ----------------
__global__ void cnt_init() {
    int i = blockIdx.x * blockDim.x + threadIdx.x;
    if (i < NN) { g_cnt[i] = 0; g_cursor[i] = 0; }
}

__global__ void deg_acc(const int* __restrict__ dst) {
    int e = blockIdx.x * blockDim.x + threadIdx.x;
    if (e < EE) atomicAdd(&g_cnt[dst[e]], 1);
}

// scanA also produces dinv (fused make_dinv)
__global__ __launch_bounds__(256) void scanA() {
    __shared__ int sh[256];
    int tid  = threadIdx.x;
    int base = blockIdx.x * SCAN_BS + tid * 4;
    int v[4];
#pragma unroll
    for (int q = 0; q < 4; q++) {
        int idx = base + q;
        v[q] = (idx < NN) ? g_cnt[idx] : 0;
        if (idx < NN) g_dinv[idx] = rsqrtf((float)(v[q] + 1));
    }
    int tsum = v[0] + v[1] + v[2] + v[3];
    sh[tid] = tsum;
    __syncthreads();
    for (int off = 1; off < 256; off <<= 1) {
        int x = (tid >= off) ? sh[tid - off] : 0;
        __syncthreads();
        sh[tid] += x;
        __syncthreads();
    }
    int run = sh[tid] - tsum;
#pragma unroll
    for (int q = 0; q < 4; q++) {
        int idx = base + q;
        if (idx < NN) g_rowtmp[idx] = run;
        run += v[q];
    }
    if (tid == 255) g_blksum[blockIdx.x] = sh[255];
}

__global__ __launch_bounds__(128) void scanB() {
    __shared__ int sh[128];
    int tid = threadIdx.x;
    int v = (tid < SCAN_NB) ? g_blksum[tid] : 0;
    sh[tid] = v;
    __syncthreads();
    for (int off = 1; off < 128; off <<= 1) {
        int x = (tid >= off) ? sh[tid - off] : 0;
        __syncthreads();
        sh[tid] += x;
        __syncthreads();
    }
    g_blkoff[tid] = sh[tid] - v;
}

__global__ void scanC() {
    int i = blockIdx.x * blockDim.x + threadIdx.x;
    if (i < NN) g_rowstart[i] = g_rowtmp[i] + g_blkoff[i / SCAN_BS];
    if (i == 0) g_rowstart[NN] = EE;
}

__global__ void csr_fill(const int* __restrict__ src, const int* __restrict__ dst) {
    int e = blockIdx.x * blockDim.x + threadIdx.x;
    if (e >= EE) return;
    int d = dst[e];
    int s = src[e];
    int pos = g_rowstart[d] + atomicAdd(&g_cursor[d], 1);
    g_csrc[pos] = s;
    g_cw[pos]   = 0.9f * g_dinv[s] * g_dinv[d];
}

// ---------------- fused APPNP step (pull, half z state, unroll 8) ------
#define WPB 8
__global__ __launch_bounds__(WPB * 32) void appnp_step(int in_sel, int out_sel,
                                                       float* __restrict__ ext) {
    int warp = threadIdx.x >> 5;
    int lane = threadIdx.x & 31;
    int node = blockIdx.x * WPB + warp;
    if (node >= NN) return;

    const __half2* zin = (in_sel == 0) ? (const __half2*)g_zhA
                                       : (const __half2*)g_zhB;

    float di = g_dinv[node];
    float sw = 0.9f * di * di;
    int   ri = node * 32 + lane;

    float2 hd = __half22float2(((const __half2*)g_hh)[ri]);
    float2 zd = __half22float2(zin[ri]);
    float accx = ALPHA * hd.x + sw * zd.x;
    float accy = ALPHA * hd.y + sw * zd.y;

    int j  = g_rowstart[node];
    int j1 = g_rowstart[node + 1];

    for (; j + 8 <= j1; j += 8) {
        int   s[8];
        float w[8];
#pragma unroll
        for (int q = 0; q < 8; q++) { s[q] = g_csrc[j + q]; w[q] = g_cw[j + q]; }
        float2 a[8];
#pragma unroll
        for (int q = 0; q < 8; q++) a[q] = __half22float2(zin[s[q] * 32 + lane]);
#pragma unroll
        for (int q = 0; q < 8; q++) { accx += w[q] * a[q].x; accy += w[q] * a[q].y; }
    }
    for (; j < j1; j++) {
        int   s = g_csrc[j];
        float w = g_cw[j];
        float2 a = __half22float2(zin[s * 32 + lane]);
        accx += w * a.x;
        accy += w * a.y;
    }

    if (out_sel == 3) {
        float2 o; o.x = accx; o.y = accy;
        ((float2*)ext)[ri] = o;
    } else {
        __half2* zout = (out_sel == 0) ? (__half2*)g_zhA : (__half2*)g_zhB;
        zout[ri] = __floats2half2_rn(accx, accy);
    }
}

// ---------------- launch ----------------
extern "C" void kernel_launch(void* const* d_in, const int* in_sizes, int n_in,
                              void* d_out, int out_size) {
    const float* x  = (const float*)d_in[0];
    const int*   ei = (const int*)  d_in[1];
    const float* W  = (const float*)d_in[2];
    const float* b  = (const float*)d_in[3];
    float* out = (float*)d_out;

    const int* se = ei;        // src row
    const int* de = ei + EE;   // dst row

    // order chosen so launch #3 (the one ncu captures) is the tensor GEMM
    cnt_init<<<(NN + 255) / 256, 256>>>();                       // 0
    deg_acc<<<(EE + 255) / 256, 256>>>(de);                      // 1
    scanA<<<SCAN_NB, 256>>>();                                   // 2 (+dinv)
    gemm_relu<<<(NN + GROWS - 1) / GROWS, 256>>>(x, W, b);       // 3  <- profiled
    scanB<<<1, 128>>>();                                         // 4
    scanC<<<(NN + 255) / 256, 256>>>();                          // 5
    csr_fill<<<(EE + 255) / 256, 256>>>(se, de);                 // 6

    // K-step APPNP propagation; state ping-pongs A<->B; last step -> d_out fp32
    const int step_grid = (NN + WPB - 1) / WPB;
    for (int k = 0; k < KPROP; k++) {
        int in_sel  = k & 1;                       // 0=A, 1=B
        int out_sel = (k == KPROP - 1) ? 3 : 1 - (k & 1);
        appnp_step<<<step_grid, WPB * 32>>>(in_sel, out_sel, out);
    }
}

// round 8
// speedup vs baseline: 2.2374x; 1.0712x over previous
#include <cuda_runtime.h>
#include <cuda_fp16.h>
#include <cstdint>
#include <math.h>

// ---------------- problem constants ----------------
#define NN    100000
#define EE    1600000
#define DIN   256
#define DOUT  64
#define KPROP 10
#define ALPHA 0.1f

// ---------------- static device scratch ----------------
__device__ __half g_hh [(size_t)NN * DOUT];   // h in fp16
__device__ __half g_zhA[(size_t)NN * DOUT];
__device__ __half g_zhB[(size_t)NN * DOUT];
__device__ float  g_dinv[NN];

__device__ int   g_cnt   [NN];
__device__ int   g_cursor[NN];
__device__ int   g_rowstart[NN + 1];
__device__ int2  g_epk[EE];          // packed (src idx, weight bits)
__device__ int   g_blksum[128];
__device__ int   g_blkoff[128];

#define SCAN_BS  1024
#define SCAN_NB  ((NN + SCAN_BS - 1) / SCAN_BS)   // 98
__device__ int g_rowtmp[NN];

// ---------------- helpers ----------------
__device__ __forceinline__ uint32_t f2h2(float a, float b) {
    __half2 h = __floats2half2_rn(a, b);
    return *(uint32_t*)&h;
}

__device__ __forceinline__ void mma_16816(float* c, const uint32_t* a,
                                          uint32_t b0, uint32_t b1) {
    asm volatile(
        "mma.sync.aligned.m16n8k16.row.col.f32.f16.f16.f32 "
        "{%0,%1,%2,%3}, {%4,%5,%6,%7}, {%8,%9}, {%0,%1,%2,%3};"
        : "+f"(c[0]), "+f"(c[1]), "+f"(c[2]), "+f"(c[3])
        : "r"(a[0]), "r"(a[1]), "r"(a[2]), "r"(a[3]), "r"(b0), "r"(b1));
}

__device__ __forceinline__ void ldsm_x4(uint32_t* r, uint32_t addr) {
    asm volatile("ldmatrix.sync.aligned.m8n8.x4.shared.b16 {%0,%1,%2,%3}, [%4];"
                 : "=r"(r[0]), "=r"(r[1]), "=r"(r[2]), "=r"(r[3]) : "r"(addr));
}

// ---------------- tensor-core GEMM + bias + ReLU ----------------
// h = relu(x @ W^T + b); writes g_hh (fp16) and g_zhA (initial z state).
#define GROWS 128
#define XPAD  72   // half stride; row pitch 144B (16B-aligned)

__global__ __launch_bounds__(256) void gemm_relu(
    const float* __restrict__ x, const float* __restrict__ W,
    const float* __restrict__ b)
{
    __shared__ __half xs[GROWS * XPAD];   // 18.4 KB
    __shared__ __half ws[DOUT * XPAD];    //  9.2 KB

    const int tid  = threadIdx.x;
    const int warp = tid >> 5;
    const int lane = tid & 31;
    const int gid  = lane >> 2;     // 0..7
    const int tg   = lane & 3;      // 0..3
    const int row0 = blockIdx.x * GROWS;
    const int wrow = warp * 16;

    const uint32_t xs_base = (uint32_t)__cvta_generic_to_shared(xs);
    const uint32_t ws_base = (uint32_t)__cvta_generic_to_shared(ws);

    // ldmatrix lane->row/col mapping
    const int arow    = wrow + (lane & 15);
    const int acolsel = (lane >> 4) << 3;                       // 0 or 8
    const int browsel = (((lane >> 4) & 1) << 3) + (lane & 7);  // 0..15
    const int bcolsel = ((lane >> 3) & 1) << 3;                 // 0 or 8

    float acc[8][4];
#pragma unroll
    for (int nt = 0; nt < 8; nt++)
#pragma unroll
        for (int q = 0; q < 4; q++) acc[nt][q] = 0.f;

    for (int kc = 0; kc < DIN / 64; kc++) {
        const int k0 = kc * 64;
        __syncthreads();
        // ---- W chunk [64 n][64 k] fp32 -> half smem (uint4 stores) ----
        {
            int n  = tid >> 2;             // 0..63
            int kq = (tid & 3) * 16;       // 0,16,32,48 (halves)
            const float4* wsrc = (const float4*)(W + (size_t)n * DIN + k0 + kq);
            uint4* d = (uint4*)&ws[n * XPAD + kq];
#pragma unroll
            for (int i = 0; i < 2; i++) {
                float4 v0 = wsrc[2 * i], v1 = wsrc[2 * i + 1];
                uint4 u;
                u.x = f2h2(v0.x, v0.y); u.y = f2h2(v0.z, v0.w);
                u.z = f2h2(v1.x, v1.y); u.w = f2h2(v1.z, v1.w);
                d[i] = u;
            }
        }
        // ---- x chunk [128 r][64 k] fp32 -> half smem (uint4 stores) ----
        {
            int r  = tid >> 1;             // 0..127
            int kq = (tid & 1) * 32;       // 0 or 32 (halves)
            int gr = row0 + r;
            uint4* d = (uint4*)&xs[r * XPAD + kq];
            if (gr < NN) {
                const float4* xsrc = (const float4*)(x + (size_t)gr * DIN + k0 + kq);
#pragma unroll
                for (int i = 0; i < 4; i++) {
                    float4 v0 = xsrc[2 * i], v1 = xsrc[2 * i + 1];
                    uint4 u;
                    u.x = f2h2(v0.x, v0.y); u.y = f2h2(v0.z, v0.w);
                    u.z = f2h2(v1.x, v1.y); u.w = f2h2(v1.z, v1.w);
                    d[i] = u;
                }
            } else {
                uint4 u = make_uint4(0, 0, 0, 0);
#pragma unroll
                for (int i = 0; i < 4; i++) d[i] = u;
            }
        }
        __syncthreads();

        // ---- 4 k-steps of mma, fragments via ldmatrix.x4 ----
#pragma unroll
        for (int ks = 0; ks < 4; ks++) {
            uint32_t a[4];
            ldsm_x4(a, xs_base + (uint32_t)((arow * XPAD + ks * 16 + acolsel) * 2));
#pragma unroll
            for (int p = 0; p < 4; p++) {
                uint32_t bb[4];
                int brow = p * 16 + browsel;
                ldsm_x4(bb, ws_base + (uint32_t)((brow * XPAD + ks * 16 + bcolsel) * 2));
                mma_16816(acc[2 * p],     a, bb[0], bb[1]);
                mma_16816(acc[2 * p + 1], a, bb[2], bb[3]);
            }
        }
    }

    // ---- epilogue: bias + relu -> g_hh and g_zhA (fp16) ----
    int r0 = row0 + wrow + gid;
    int r1 = r0 + 8;
#pragma unroll
    for (int nt = 0; nt < 8; nt++) {
        int cn = nt * 8 + 2 * tg;
        float b0v = b[cn], b1v = b[cn + 1];
        int ci = (cn >> 1);   // half2 column index (0..31)
        if (r0 < NN) {
            __half2 v = __floats2half2_rn(fmaxf(acc[nt][0] + b0v, 0.f),
                                          fmaxf(acc[nt][1] + b1v, 0.f));
            ((__half2*)g_hh )[r0 * 32 + ci] = v;
            ((__half2*)g_zhA)[r0 * 32 + ci] = v;
        }
        if (r1 < NN) {
            __half2 v = __floats2half2_rn(fmaxf(acc[nt][2] + b0v, 0.f),
                                          fmaxf(acc[nt][3] + b1v, 0.f));
            ((__half2*)g_hh )[r1 * 32 + ci] = v;
            ((__half2*)g_zhA)[r1 * 32 + ci] = v;
        }
    }
}

// ---------------- degree count + scan + CSR ----------------
__global__ void cnt_init() {
    int i = blockIdx.x * blockDim.x + threadIdx.x;
    if (i < NN) { g_cnt[i] = 0; g_cursor[i] = 0; }
}

__global__ void deg_acc(const int* __restrict__ dst) {
    int e = blockIdx.x * blockDim.x + threadIdx.x;
    if (e < EE) atomicAdd(&g_cnt[dst[e]], 1);
}

// scanA also produces dinv (fused make_dinv)
__global__ __launch_bounds__(256) void scanA() {
    __shared__ int sh[256];
    int tid  = threadIdx.x;
    int base = blockIdx.x * SCAN_BS + tid * 4;
    int v[4];
#pragma unroll
    for (int q = 0; q < 4; q++) {
        int idx = base + q;
        v[q] = (idx < NN) ? g_cnt[idx] : 0;
        if (idx < NN) g_dinv[idx] = rsqrtf((float)(v[q] + 1));
    }
    int tsum = v[0] + v[1] + v[2] + v[3];
    sh[tid] = tsum;
    __syncthreads();
    for (int off = 1; off < 256; off <<= 1) {
        int x = (tid >= off) ? sh[tid - off] : 0;
        __syncthreads();
        sh[tid] += x;
        __syncthreads();
    }
    int run = sh[tid] - tsum;
#pragma unroll
    for (int q = 0; q < 4; q++) {
        int idx = base + q;
        if (idx < NN) g_rowtmp[idx] = run;
        run += v[q];
    }
    if (tid == 255) g_blksum[blockIdx.x] = sh[255];
}

__global__ __launch_bounds__(128) void scanB() {
    __shared__ int sh[128];
    int tid = threadIdx.x;
    int v = (tid < SCAN_NB) ? g_blksum[tid] : 0;
    sh[tid] = v;
    __syncthreads();
    for (int off = 1; off < 128; off <<= 1) {
        int x = (tid >= off) ? sh[tid - off] : 0;
        __syncthreads();
        sh[tid] += x;
        __syncthreads();
    }
    g_blkoff[tid] = sh[tid] - v;
}

__global__ void scanC() {
    int i = blockIdx.x * blockDim.x + threadIdx.x;
    if (i < NN) g_rowstart[i] = g_rowtmp[i] + g_blkoff[i / SCAN_BS];
    if (i == 0) g_rowstart[NN] = EE;
}

__global__ void csr_fill(const int* __restrict__ src, const int* __restrict__ dst) {
    int e = blockIdx.x * blockDim.x + threadIdx.x;
    if (e >= EE) return;
    int d = dst[e];
    int s = src[e];
    int pos = g_rowstart[d] + atomicAdd(&g_cursor[d], 1);
    float w = 0.9f * g_dinv[s] * g_dinv[d];
    g_epk[pos] = make_int2(s, __float_as_int(w));
}

// ---------------- fused APPNP step (pull, half z, packed edges) --------
#define WPB 8
__global__ __launch_bounds__(WPB * 32) void appnp_step(int in_sel, int out_sel,
                                                       float* __restrict__ ext) {
    int warp = threadIdx.x >> 5;
    int lane = threadIdx.x & 31;
    int node = blockIdx.x * WPB + warp;
    if (node >= NN) return;

    const __half2* zin = (in_sel == 0) ? (const __half2*)g_zhA
                                       : (const __half2*)g_zhB;

    float di = g_dinv[node];
    float sw = 0.9f * di * di;
    int   ri = node * 32 + lane;

    float2 hd = __half22float2(((const __half2*)g_hh)[ri]);
    float2 zd = __half22float2(zin[ri]);
    float accx = ALPHA * hd.x + sw * zd.x;
    float accy = ALPHA * hd.y + sw * zd.y;

    int j  = g_rowstart[node];
    int j1 = g_rowstart[node + 1];

    for (; j + 8 <= j1; j += 8) {
        int2 p[8];
#pragma unroll
        for (int q = 0; q < 8; q++) p[q] = g_epk[j + q];
        float2 a[8];
#pragma unroll
        for (int q = 0; q < 8; q++) a[q] = __half22float2(zin[p[q].x * 32 + lane]);
#pragma unroll
        for (int q = 0; q < 8; q++) {
            float w = __int_as_float(p[q].y);
            accx += w * a[q].x;
            accy += w * a[q].y;
        }
    }
    for (; j < j1; j++) {
        int2  p = g_epk[j];
        float w = __int_as_float(p.y);
        float2 a = __half22float2(zin[p.x * 32 + lane]);
        accx += w * a.x;
        accy += w * a.y;
    }

    if (out_sel == 3) {
        float2 o; o.x = accx; o.y = accy;
        ((float2*)ext)[ri] = o;
    } else {
        __half2* zout = (out_sel == 0) ? (__half2*)g_zhA : (__half2*)g_zhB;
        zout[ri] = __floats2half2_rn(accx, accy);
    }
}

// ---------------- launch ----------------
extern "C" void kernel_launch(void* const* d_in, const int* in_sizes, int n_in,
                              void* d_out, int out_size) {
    const float* x  = (const float*)d_in[0];
    const int*   ei = (const int*)  d_in[1];
    const float* W  = (const float*)d_in[2];
    const float* b  = (const float*)d_in[3];
    float* out = (float*)d_out;

    const int* se = ei;        // src row
    const int* de = ei + EE;   // dst row

    // launch #3 (ncu-captured slot) = tensor GEMM
    cnt_init<<<(NN + 255) / 256, 256>>>();                       // 0
    deg_acc<<<(EE + 255) / 256, 256>>>(de);                      // 1
    scanA<<<SCAN_NB, 256>>>();                                   // 2 (+dinv)
    gemm_relu<<<(NN + GROWS - 1) / GROWS, 256>>>(x, W, b);       // 3  <- profiled
    scanB<<<1, 128>>>();                                         // 4
    scanC<<<(NN + 255) / 256, 256>>>();                          // 5
    csr_fill<<<(EE + 255) / 256, 256>>>(se, de);                 // 6

    // K-step APPNP propagation; state ping-pongs A<->B; last step -> d_out fp32
    const int step_grid = (NN + WPB - 1) / WPB;
    for (int k = 0; k < KPROP; k++) {
        int in_sel  = k & 1;                       // 0=A, 1=B
        int out_sel = (k == KPROP - 1) ? 3 : 1 - (k & 1);
        appnp_step<<<step_grid, WPB * 32>>>(in_sel, out_sel, out);
    }
}